// round 7
// baseline (speedup 1.0000x reference)
#include <cuda_runtime.h>

#define Bc 4
#define Tc 2048
#define Cc 1024
#define Dc 64
#define BT (Bc*Tc)

#define QT   128           // q rows per attention block
#define NQ2  (Tc/QT)       // 16 q-blocks per batch
#define SCH  4             // k-tiles (of 64 keys) per chunk
#define MAXC2 8            // max chunks per q-block
#define SKS  68            // K smem row stride (=4 mod 32)
#define SVS  72            // V smem row stride (=8 mod 32)
#define SA   44            // qkv A smem row stride (=12 mod 32)
#define SB   72            // qkv B smem row stride (=8 mod 32)
#define NS   3             // qkv pipeline stages

// Scratch (allocation-free rule => __device__ globals)
__device__ float g_Wr[3*Cc*Dc];                       // tf32-rounded weights
__device__ float g_Q[BT*Dc];
__device__ float g_K[BT*Dc];
__device__ float g_V[BT*Dc];
__device__ float g_Op2[(size_t)Bc*NQ2*MAXC2*QT*Dc];   // unnormalized partial O
__device__ float g_m2[Bc*NQ2*MAXC2*QT];
__device__ float g_l2[Bc*NQ2*MAXC2*QT];

__device__ __forceinline__ unsigned f2tf32(float v) {
    unsigned u;
    asm("cvt.rna.tf32.f32 %0, %1;" : "=r"(u) : "f"(v));
    return u;
}

__device__ __forceinline__ void mma_tf32(float c[4], unsigned a0, unsigned a1,
                                         unsigned a2, unsigned a3,
                                         unsigned b0, unsigned b1) {
    asm volatile(
        "mma.sync.aligned.m16n8k8.row.col.f32.tf32.tf32.f32 "
        "{%0,%1,%2,%3}, {%4,%5,%6,%7}, {%8,%9}, {%0,%1,%2,%3};"
        : "+f"(c[0]), "+f"(c[1]), "+f"(c[2]), "+f"(c[3])
        : "r"(a0), "r"(a1), "r"(a2), "r"(a3), "r"(b0), "r"(b1));
}

__device__ __forceinline__ void cp16(float* dst_smem, const float* src) {
    unsigned d = (unsigned)__cvta_generic_to_shared(dst_smem);
    asm volatile("cp.async.ca.shared.global [%0], [%1], 16;" :: "r"(d), "l"(src));
}
#define CP_COMMIT() asm volatile("cp.async.commit_group;")
#define CP_WAIT1()  asm volatile("cp.async.wait_group 1;")

// ---------------------------------------------------------------------------
// Kernel 0: pre-round W matrices to tf32.
// ---------------------------------------------------------------------------
__global__ __launch_bounds__(256) void roundw_kernel(
    const float* __restrict__ Wq, const float* __restrict__ Wk,
    const float* __restrict__ Wv)
{
    const float* src = (blockIdx.y == 0) ? Wq : (blockIdx.y == 1) ? Wk : Wv;
    float* dst = g_Wr + (size_t)blockIdx.y * Cc * Dc;
    int idx = blockIdx.x * 256 + threadIdx.x;
    float4 v = ((const float4*)src)[idx];
    uint4 r;
    r.x = f2tf32(v.x); r.y = f2tf32(v.y); r.z = f2tf32(v.z); r.w = f2tf32(v.w);
    ((uint4*)dst)[idx] = r;
}

// ---------------------------------------------------------------------------
// Kernel 1: QKV projection, TF32 MMA, 3-stage cp.async pipeline.
// grid = (BT/64, 3) = (128,3), block = 128 (4 warps). Tile 64x64, BK=32.
// Prefetch distance 2 (~500 cyc), one __syncthreads per K-iteration,
// smem 61.4 KB -> 3 CTAs/SM -> all 384 CTAs resident in one wave.
// ---------------------------------------------------------------------------
__global__ __launch_bounds__(128) void qkv_kernel(
    const float* __restrict__ x,
    const float* __restrict__ bq, const float* __restrict__ bk,
    const float* __restrict__ bv)
{
    extern __shared__ __align__(16) float sm[];
    float* As = sm;                   // [NS][64*SA]
    float* Bs = sm + NS*64*SA;        // [NS][32*SB]

    const int tid = threadIdx.x;
    const int which = blockIdx.y;
    const float* W = g_Wr + (size_t)which * Cc * Dc;
    const float* bias;  float* O;
    if (which == 0)      { bias = bq; O = g_Q; }
    else if (which == 1) { bias = bk; O = g_K; }
    else                 { bias = bv; O = g_V; }
    const float osc = (which == 0) ? 0.125f : 1.0f;

    const int m0 = blockIdx.x * 64;
    const int w  = tid >> 5;
    const int lane = tid & 31;
    const int g  = lane >> 2;
    const int tg = lane & 3;
    const int wm = (w & 1) * 32;
    const int wn = (w >> 1) * 32;

    // cp.async mappings (128 threads)
    const int a_row = tid >> 3, a_c8 = tid & 7;     // A: 64x32, 4 chunks/thread
    const int b_row = tid >> 4, b_c16 = tid & 15;   // B: 32x64, 4 chunks/thread

    float acc[2][4][4];
    #pragma unroll
    for (int mt = 0; mt < 2; ++mt)
        #pragma unroll
        for (int nt = 0; nt < 4; ++nt)
            #pragma unroll
            for (int q = 0; q < 4; ++q) acc[mt][nt][q] = 0.f;

    const int NIT = Cc/32;

    // Prologue: stage kc = 0, 1 into buffers 0, 1
    #pragma unroll
    for (int p = 0; p < NS-1; ++p) {
        float* Ad = As + p*64*SA;
        float* Bd = Bs + p*32*SB;
        #pragma unroll
        for (int j = 0; j < 4; ++j) {
            int row = a_row + 16*j;
            cp16(&Ad[row*SA + a_c8*4], &x[(size_t)(m0 + row)*Cc + p*32 + a_c8*4]);
        }
        #pragma unroll
        for (int j = 0; j < 4; ++j) {
            int row = b_row + 8*j;
            cp16(&Bd[row*SB + b_c16*4], &W[(size_t)(p*32 + row)*Dc + b_c16*4]);
        }
        CP_COMMIT();
    }

    for (int kc = 0; kc < NIT; ++kc) {
        CP_WAIT1();        // group kc complete (kc+1 may stay in flight)
        __syncthreads();   // all warps done computing kc-1; smem for kc visible

        const int buf = kc % NS;
        float* Ab = As + buf*64*SA;
        float* Bb = Bs + buf*32*SB;

        // Prefetch stage kc+2 into buffer (kc+2)%NS (== (kc-1)%NS, safe post-sync)
        if (kc + 2 < NIT) {
            const int nbuf = (kc + 2) % NS;
            float* An = As + nbuf*64*SA;
            float* Bn = Bs + nbuf*32*SB;
            #pragma unroll
            for (int j = 0; j < 4; ++j) {
                int row = a_row + 16*j;
                cp16(&An[row*SA + a_c8*4],
                     &x[(size_t)(m0 + row)*Cc + (kc+2)*32 + a_c8*4]);
            }
            #pragma unroll
            for (int j = 0; j < 4; ++j) {
                int row = b_row + 8*j;
                cp16(&Bn[row*SB + b_c16*4],
                     &W[(size_t)((kc+2)*32 + row)*Dc + b_c16*4]);
            }
        }
        CP_COMMIT();       // empty group near the tail keeps wait count uniform

        #pragma unroll
        for (int ks = 0; ks < 4; ++ks) {
            const int k0 = ks * 8;
            unsigned a[2][4], b[4][2];
            #pragma unroll
            for (int mt = 0; mt < 2; ++mt) {
                const float* base = &Ab[(wm + mt*16 + g)*SA + k0 + tg];
                a[mt][0] = __float_as_uint(base[0]);
                a[mt][1] = __float_as_uint(base[8*SA]);
                a[mt][2] = __float_as_uint(base[4]);
                a[mt][3] = __float_as_uint(base[8*SA + 4]);
            }
            #pragma unroll
            for (int nt = 0; nt < 4; ++nt) {
                const float* base = &Bb[(k0 + tg)*SB + wn + nt*8 + g];
                b[nt][0] = __float_as_uint(base[0]);
                b[nt][1] = __float_as_uint(base[4*SB]);
            }
            #pragma unroll
            for (int mt = 0; mt < 2; ++mt)
                #pragma unroll
                for (int nt = 0; nt < 4; ++nt)
                    mma_tf32(acc[mt][nt], a[mt][0], a[mt][1], a[mt][2], a[mt][3],
                             b[nt][0], b[nt][1]);
        }
    }

    // Writeback: (acc+bias)*osc, rna-rounded tf32.
    #pragma unroll
    for (int nt = 0; nt < 4; ++nt) {
        const int col = wn + nt*8 + 2*tg;
        float bx = bias[col], by = bias[col+1];
        #pragma unroll
        for (int mt = 0; mt < 2; ++mt) {
            int row = m0 + wm + mt*16 + g;
            float2 o0, o1;
            o0.x = __uint_as_float(f2tf32((acc[mt][nt][0] + bx) * osc));
            o0.y = __uint_as_float(f2tf32((acc[mt][nt][1] + by) * osc));
            o1.x = __uint_as_float(f2tf32((acc[mt][nt][2] + bx) * osc));
            o1.y = __uint_as_float(f2tf32((acc[mt][nt][3] + by) * osc));
            *(float2*)&O[(size_t)row*Dc + col]      = o0;
            *(float2*)&O[(size_t)(row+8)*Dc + col]  = o1;
        }
    }
}

// ---------------------------------------------------------------------------
// Kernel 2: TF32 tensor-core flash attention, split-KV, cp.async pipeline.
// grid = (MAXC2, NQ2, B), block = 256 (8 warps). (unchanged)
// ---------------------------------------------------------------------------
__global__ __launch_bounds__(256, 2) void attn_kernel()
{
    const int c = blockIdx.x;
    const int i = blockIdx.y;
    const int b = blockIdx.z;
    const int ktot = 2*(i+1);
    const int kt0 = c * SCH;
    if (kt0 >= ktot) return;
    const int kt1 = min(kt0 + SCH, ktot);

    extern __shared__ __align__(16) float smem[];
    float* Ksm = smem;                 // [2][64*SKS]
    float* Vsm = smem + 2*64*SKS;      // [2][64*SVS]

    const int tid = threadIdx.x;
    const int w = tid >> 5, lane = tid & 31;
    const int g = lane >> 2, tg = lane & 3;
    const int qrow = i*QT + w*16;
    const size_t bT = (size_t)b * Tc;

    const int l_row = tid >> 2, l_c4 = tid & 3;

    {
        const float* Kg = &g_K[(bT + kt0*64)*Dc];
        const float* Vg = &g_V[(bT + kt0*64)*Dc];
        #pragma unroll
        for (int j = 0; j < 4; ++j)
            cp16(&Ksm[l_row*SKS + (l_c4*4 + j)*4], &Kg[(size_t)l_row*Dc + (l_c4*4 + j)*4]);
        #pragma unroll
        for (int j = 0; j < 4; ++j)
            cp16(&Vsm[l_row*SVS + (l_c4*4 + j)*4], &Vg[(size_t)l_row*Dc + (l_c4*4 + j)*4]);
        CP_COMMIT();
    }

    unsigned qa[8][4];
    {
        const float* Qp = &g_Q[(bT + qrow)*Dc];
        #pragma unroll
        for (int kc = 0; kc < 8; ++kc) {
            qa[kc][0] = __float_as_uint(Qp[(g  )*Dc + kc*8+tg  ]);
            qa[kc][1] = __float_as_uint(Qp[(g+8)*Dc + kc*8+tg  ]);
            qa[kc][2] = __float_as_uint(Qp[(g  )*Dc + kc*8+tg+4]);
            qa[kc][3] = __float_as_uint(Qp[(g+8)*Dc + kc*8+tg+4]);
        }
    }

    float o[8][4];
    #pragma unroll
    for (int nt = 0; nt < 8; ++nt)
        #pragma unroll
        for (int q = 0; q < 4; ++q) o[nt][q] = 0.f;
    float m0v = -1e30f, m1v = -1e30f, l0 = 0.f, l1 = 0.f;

    for (int kt = kt0; kt < kt1; ++kt) {
        const int buf = (kt - kt0) & 1;
        const float* ks = Ksm + buf*64*SKS;
        const float* vs = Vsm + buf*64*SVS;
        float* kn = Ksm + (buf^1)*64*SKS;
        float* vn = Vsm + (buf^1)*64*SVS;

        __syncthreads();
        if (kt + 1 < kt1) {
            const float* Kg = &g_K[(bT + (kt+1)*64)*Dc];
            const float* Vg = &g_V[(bT + (kt+1)*64)*Dc];
            #pragma unroll
            for (int j = 0; j < 4; ++j)
                cp16(&kn[l_row*SKS + (l_c4*4 + j)*4], &Kg[(size_t)l_row*Dc + (l_c4*4 + j)*4]);
            #pragma unroll
            for (int j = 0; j < 4; ++j)
                cp16(&vn[l_row*SVS + (l_c4*4 + j)*4], &Vg[(size_t)l_row*Dc + (l_c4*4 + j)*4]);
        }
        CP_COMMIT();
        CP_WAIT1();
        __syncthreads();

        const int kb = kt * 64;
        if (kb <= qrow + 15) {
            float s[8][4];
            #pragma unroll
            for (int nt = 0; nt < 8; ++nt)
                { s[nt][0]=0.f; s[nt][1]=0.f; s[nt][2]=0.f; s[nt][3]=0.f; }
            #pragma unroll
            for (int kc = 0; kc < 8; ++kc) {
                #pragma unroll
                for (int nt = 0; nt < 8; ++nt) {
                    const float* kp = &ks[(nt*8 + g)*SKS + kc*8 + tg];
                    mma_tf32(s[nt], qa[kc][0], qa[kc][1], qa[kc][2], qa[kc][3],
                             __float_as_uint(kp[0]), __float_as_uint(kp[4]));
                }
            }

            if (kb + 63 > qrow) {
                const int r0 = qrow + g, r1 = r0 + 8;
                #pragma unroll
                for (int nt = 0; nt < 8; ++nt) {
                    int col = kb + nt*8 + 2*tg;
                    if (col   > r0) s[nt][0] = -1e30f;
                    if (col+1 > r0) s[nt][1] = -1e30f;
                    if (col   > r1) s[nt][2] = -1e30f;
                    if (col+1 > r1) s[nt][3] = -1e30f;
                }
            }

            float rm0 = -1e30f, rm1 = -1e30f;
            #pragma unroll
            for (int nt = 0; nt < 8; ++nt) {
                rm0 = fmaxf(rm0, fmaxf(s[nt][0], s[nt][1]));
                rm1 = fmaxf(rm1, fmaxf(s[nt][2], s[nt][3]));
            }
            rm0 = fmaxf(rm0, __shfl_xor_sync(0xffffffffu, rm0, 1));
            rm0 = fmaxf(rm0, __shfl_xor_sync(0xffffffffu, rm0, 2));
            rm1 = fmaxf(rm1, __shfl_xor_sync(0xffffffffu, rm1, 1));
            rm1 = fmaxf(rm1, __shfl_xor_sync(0xffffffffu, rm1, 2));
            const float mn0 = fmaxf(m0v, rm0), mn1 = fmaxf(m1v, rm1);
            const float f0 = __expf(m0v - mn0), f1 = __expf(m1v - mn1);
            m0v = mn0; m1v = mn1;

            float rs0 = 0.f, rs1 = 0.f;
            #pragma unroll
            for (int nt = 0; nt < 8; ++nt) {
                s[nt][0] = __uint_as_float(f2tf32(__expf(s[nt][0] - mn0)));
                s[nt][1] = __uint_as_float(f2tf32(__expf(s[nt][1] - mn0)));
                s[nt][2] = __uint_as_float(f2tf32(__expf(s[nt][2] - mn1)));
                s[nt][3] = __uint_as_float(f2tf32(__expf(s[nt][3] - mn1)));
                rs0 += s[nt][0] + s[nt][1];
                rs1 += s[nt][2] + s[nt][3];
            }
            rs0 += __shfl_xor_sync(0xffffffffu, rs0, 1);
            rs0 += __shfl_xor_sync(0xffffffffu, rs0, 2);
            rs1 += __shfl_xor_sync(0xffffffffu, rs1, 1);
            rs1 += __shfl_xor_sync(0xffffffffu, rs1, 2);
            l0 = l0*f0 + rs0;
            l1 = l1*f1 + rs1;
            #pragma unroll
            for (int nt = 0; nt < 8; ++nt) {
                o[nt][0] *= f0; o[nt][1] *= f0;
                o[nt][2] *= f1; o[nt][3] *= f1;
            }

            const int src0 = (lane & ~3) | (tg >> 1);
            const int src1 = src0 + 2;
            const bool odd = (tg & 1);
            #pragma unroll
            for (int kc = 0; kc < 8; ++kc) {
                float t00 = __shfl_sync(0xffffffffu, s[kc][0], src0);
                float t01 = __shfl_sync(0xffffffffu, s[kc][1], src0);
                float t20 = __shfl_sync(0xffffffffu, s[kc][2], src0);
                float t21 = __shfl_sync(0xffffffffu, s[kc][3], src0);
                float u00 = __shfl_sync(0xffffffffu, s[kc][0], src1);
                float u01 = __shfl_sync(0xffffffffu, s[kc][1], src1);
                float u20 = __shfl_sync(0xffffffffu, s[kc][2], src1);
                float u21 = __shfl_sync(0xffffffffu, s[kc][3], src1);
                s[kc][0] = odd ? t01 : t00;
                s[kc][1] = odd ? t21 : t20;
                s[kc][2] = odd ? u01 : u00;
                s[kc][3] = odd ? u21 : u20;
            }

            #pragma unroll
            for (int kc = 0; kc < 8; ++kc) {
                #pragma unroll
                for (int nt = 0; nt < 8; ++nt) {
                    const float* vp = &vs[(kc*8 + tg)*SVS + nt*8 + g];
                    mma_tf32(o[nt],
                             __float_as_uint(s[kc][0]), __float_as_uint(s[kc][1]),
                             __float_as_uint(s[kc][2]), __float_as_uint(s[kc][3]),
                             __float_as_uint(vp[0]), __float_as_uint(vp[4*SVS]));
                }
            }
        }
    }

    const size_t pbase = ((size_t)(b*NQ2 + i)*MAXC2 + c) * (QT*Dc);
    #pragma unroll
    for (int nt = 0; nt < 8; ++nt) {
        const int colb = nt*8 + 2*tg;
        float2 o0; o0.x = o[nt][0]; o0.y = o[nt][1];
        float2 o1; o1.x = o[nt][2]; o1.y = o[nt][3];
        *(float2*)&g_Op2[pbase + (size_t)(w*16 + g    )*Dc + colb] = o0;
        *(float2*)&g_Op2[pbase + (size_t)(w*16 + g + 8)*Dc + colb] = o1;
    }
    if (tg == 0) {
        const size_t rb = ((size_t)(b*NQ2 + i)*MAXC2 + c) * QT + w*16;
        g_m2[rb + g]     = m0v;  g_l2[rb + g]     = l0;
        g_m2[rb + g + 8] = m1v;  g_l2[rb + g + 8] = l1;
    }
}

// ---------------------------------------------------------------------------
// Kernel 3: combine split-KV partials, parallelized.
// grid = (NQ2, B, 8), block = 256.
// ---------------------------------------------------------------------------
__global__ __launch_bounds__(256) void combine_kernel(float* __restrict__ out)
{
    const int i = blockIdx.x;
    const int b = blockIdx.y;
    const int nc = (2*(i+1) + SCH - 1) / SCH;
    const size_t cb = (size_t)(b*NQ2 + i) * MAXC2;

    const int f = blockIdx.z * 256 + threadIdx.x;   // float4 index in [0, 2048)
    const int row = f >> 4;

    float M = -1e30f;
    float mm[MAXC2];
    #pragma unroll
    for (int cc = 0; cc < MAXC2; ++cc) {
        if (cc < nc) {
            mm[cc] = g_m2[(cb + cc)*QT + row];
            M = fmaxf(M, mm[cc]);
        }
    }
    float L = 0.f;
    float4 o; o.x = o.y = o.z = o.w = 0.f;
    #pragma unroll
    for (int cc = 0; cc < MAXC2; ++cc) {
        if (cc < nc) {
            float wgt = __expf(mm[cc] - M);
            L += wgt * g_l2[(cb + cc)*QT + row];
            float4 p = ((const float4*)g_Op2)[(cb + cc)*(QT*Dc/4) + f];
            o.x += wgt*p.x; o.y += wgt*p.y; o.z += wgt*p.z; o.w += wgt*p.w;
        }
    }
    float inv = 1.f / L;
    o.x *= inv; o.y *= inv; o.z *= inv; o.w *= inv;
    ((float4*)out)[((size_t)b*Tc + i*QT + row)*(Dc/4) + (f & 15)] = o;
}

// ---------------------------------------------------------------------------
extern "C" void kernel_launch(void* const* d_in, const int* in_sizes, int n_in,
                              void* d_out, int out_size)
{
    const float* x  = (const float*)d_in[0];
    const float* Wq = (const float*)d_in[1];
    const float* bq = (const float*)d_in[2];
    const float* Wk = (const float*)d_in[3];
    const float* bk = (const float*)d_in[4];
    const float* Wv = (const float*)d_in[5];
    const float* bv = (const float*)d_in[6];
    float* out = (float*)d_out;

    dim3 g0(Cc*Dc/4/256, 3);
    roundw_kernel<<<g0, 256>>>(Wq, Wk, Wv);

    const int qkv_smem = (NS*64*SA + NS*32*SB) * (int)sizeof(float);  // 61,440
    cudaFuncSetAttribute(qkv_kernel, cudaFuncAttributeMaxDynamicSharedMemorySize, qkv_smem);
    dim3 g1(BT/64, 3);
    qkv_kernel<<<g1, 128, qkv_smem>>>(x, bq, bk, bv);

    const int attn_smem = (2*64*SKS + 2*64*SVS) * (int)sizeof(float); // 71,680
    cudaFuncSetAttribute(attn_kernel, cudaFuncAttributeMaxDynamicSharedMemorySize, attn_smem);
    dim3 g2(MAXC2, NQ2, Bc);
    attn_kernel<<<g2, 256, attn_smem>>>();

    dim3 g3(NQ2, Bc, 8);
    combine_kernel<<<g3, 256>>>(out);
}

// round 10
// speedup vs baseline: 1.3106x; 1.3106x over previous
#include <cuda_runtime.h>
#include <cuda_fp16.h>
#include <cstdint>

#define Bc 4
#define Tc 2048
#define Cc 1024
#define Dc 64
#define BT (Bc*Tc)

#define QT   128
#define NQ2  (Tc/QT)
#define SCH  4
#define MAXC2 8
#define SKS2 72            // attn K/VT smem row stride in halves (144B)
#define SA2  40            // qkv smem row stride in halves (80B)
#define BKH  32            // qkv k-chunk in halves

// Scratch (allocation-free rule => __device__ globals)
__device__ __half g_xh [(size_t)BT*Cc];              // fp16 x
__device__ __half g_WhT[3*Dc*Cc];                    // fp16 W^T [proj][n][k]
__device__ __half g_Qh [BT*Dc];                      // fp16 Q (pre-scaled)
__device__ __half g_Kh [BT*Dc];
__device__ __half g_Vh [BT*Dc];
__device__ __half g_VTh[BT*Dc];                      // V^T per batch: [b][d][t]
__device__ float  g_Op2[(size_t)Bc*NQ2*MAXC2*QT*Dc];
__device__ float  g_m2[Bc*NQ2*MAXC2*QT];
__device__ float  g_l2[Bc*NQ2*MAXC2*QT];

__device__ __forceinline__ unsigned packh2(float lo, float hi) {
    __half2 h = __floats2half2_rn(lo, hi);
    return *(unsigned*)&h;
}

__device__ __forceinline__ void mma_f16(float c[4], unsigned a0, unsigned a1,
                                        unsigned a2, unsigned a3,
                                        unsigned b0, unsigned b1) {
    asm volatile(
        "mma.sync.aligned.m16n8k16.row.col.f32.f16.f16.f32 "
        "{%0,%1,%2,%3}, {%4,%5,%6,%7}, {%8,%9}, {%0,%1,%2,%3};"
        : "+f"(c[0]), "+f"(c[1]), "+f"(c[2]), "+f"(c[3])
        : "r"(a0), "r"(a1), "r"(a2), "r"(a3), "r"(b0), "r"(b1));
}

__device__ __forceinline__ void cp16(void* dst_smem, const void* src) {
    unsigned d = (unsigned)__cvta_generic_to_shared(dst_smem);
    asm volatile("cp.async.ca.shared.global [%0], [%1], 16;" :: "r"(d), "l"(src));
}
#define CP_COMMIT() asm volatile("cp.async.commit_group;")
#define CP_WAIT1()  asm volatile("cp.async.wait_group 1;")

// ---------------------------------------------------------------------------
// Kernel 0a: x -> fp16.  grid = BT*Cc/8/256 = 4096, block 256.
// ---------------------------------------------------------------------------
__global__ __launch_bounds__(256) void prepx_kernel(const float* __restrict__ x)
{
    size_t idx = (size_t)blockIdx.x * 256 + threadIdx.x;   // 8 halves per thread
    const float4* xg = (const float4*)x;
    float4 v0 = xg[2*idx], v1 = xg[2*idx + 1];
    __half2 h0 = __floats2half2_rn(v0.x, v0.y);
    __half2 h1 = __floats2half2_rn(v0.z, v0.w);
    __half2 h2 = __floats2half2_rn(v1.x, v1.y);
    __half2 h3 = __floats2half2_rn(v1.z, v1.w);
    uint4 o;
    o.x = *(unsigned*)&h0; o.y = *(unsigned*)&h1;
    o.z = *(unsigned*)&h2; o.w = *(unsigned*)&h3;
    ((uint4*)g_xh)[idx] = o;
}

// ---------------------------------------------------------------------------
// Kernel 0b: W^T -> fp16.  grid = 3*Dc*Cc/256 = 768, block 256.
// ---------------------------------------------------------------------------
__global__ __launch_bounds__(256) void prepw_kernel(
    const float* __restrict__ Wq, const float* __restrict__ Wk,
    const float* __restrict__ Wv)
{
    int e = blockIdx.x * 256 + threadIdx.x;
    int proj = e >> 16;
    int r = e & 65535;
    int k = r >> 6;
    int n = r & 63;
    const float* W = (proj == 0) ? Wq : (proj == 1) ? Wk : Wv;
    g_WhT[(size_t)proj*(Dc*Cc) + (size_t)n*Cc + k] = __float2half_rn(W[(size_t)k*Dc + n]);
}

// ---------------------------------------------------------------------------
// Kernel 1: QKV projection, fp16 m16n8k16 MMA, 2-stage cp.async.
// grid = (BT/64, 3), block = 128 (4 warps). Tile 64x64, k-chunk 32 halves.
// ---------------------------------------------------------------------------
__global__ __launch_bounds__(128) void qkv_kernel(
    const float* __restrict__ bq, const float* __restrict__ bk,
    const float* __restrict__ bv)
{
    extern __shared__ __align__(16) __half sm[];
    __half* As = sm;                    // [2][64*SA2]
    __half* Bs = sm + 2*64*SA2;         // [2][64*SA2]

    const int tid = threadIdx.x;
    const int which = blockIdx.y;
    const __half* WT = g_WhT + (size_t)which * (Dc*Cc);
    const float* bias = (which == 0) ? bq : (which == 1) ? bk : bv;
    __half* O = (which == 0) ? g_Qh : (which == 1) ? g_Kh : g_Vh;
    const float osc = (which == 0) ? 0.125f : 1.0f;

    const int m0 = blockIdx.x * 64;
    const int w  = tid >> 5;
    const int lane = tid & 31;
    const int g  = lane >> 2;
    const int tg = lane & 3;
    const int wm = (w & 1) * 32;
    const int wn = (w >> 1) * 32;

    // 128 threads: l_row in [0,32), j loop covers rows 32..63
    const int l_row = tid >> 2, l_c16 = tid & 3;

    float acc[2][4][4];
    #pragma unroll
    for (int mt = 0; mt < 2; ++mt)
        #pragma unroll
        for (int nt = 0; nt < 4; ++nt)
            #pragma unroll
            for (int q = 0; q < 4; ++q) acc[mt][nt][q] = 0.f;

    // Prologue: stage kc=0 (A and B tiles: 64 rows x 32 halves each)
    {
        #pragma unroll
        for (int j = 0; j < 2; ++j) {
            int row = l_row + 32*j;
            cp16(&As[row*SA2 + l_c16*8], &g_xh[(size_t)(m0 + row)*Cc + l_c16*8]);
            cp16(&Bs[row*SA2 + l_c16*8], &WT[(size_t)row*Cc + l_c16*8]);
        }
        CP_COMMIT();
    }

    const int NIT = Cc / BKH;            // 32
    for (int kc = 0; kc < NIT; ++kc) {
        const int buf = kc & 1;
        __half* Ab = As + buf*64*SA2;
        __half* Bb = Bs + buf*64*SA2;
        __half* An = As + (buf^1)*64*SA2;
        __half* Bn = Bs + (buf^1)*64*SA2;

        __syncthreads();
        if (kc + 1 < NIT) {
            #pragma unroll
            for (int j = 0; j < 2; ++j) {
                int row = l_row + 32*j;
                cp16(&An[row*SA2 + l_c16*8],
                     &g_xh[(size_t)(m0 + row)*Cc + (kc+1)*BKH + l_c16*8]);
                cp16(&Bn[row*SA2 + l_c16*8],
                     &WT[(size_t)row*Cc + (kc+1)*BKH + l_c16*8]);
            }
        }
        CP_COMMIT();
        CP_WAIT1();
        __syncthreads();

        #pragma unroll
        for (int ks = 0; ks < 2; ++ks) {      // two k16 steps per 32-half chunk
            const int k0 = ks * 16;
            unsigned a[2][4], b[4][2];
            #pragma unroll
            for (int mt = 0; mt < 2; ++mt) {
                const __half* base = &Ab[(wm + mt*16 + g)*SA2 + k0 + 2*tg];
                a[mt][0] = *(const unsigned*)(base);
                a[mt][1] = *(const unsigned*)(base + 8*SA2);
                a[mt][2] = *(const unsigned*)(base + 8);
                a[mt][3] = *(const unsigned*)(base + 8*SA2 + 8);
            }
            #pragma unroll
            for (int nt = 0; nt < 4; ++nt) {
                const __half* base = &Bb[(wn + nt*8 + g)*SA2 + k0 + 2*tg];
                b[nt][0] = *(const unsigned*)(base);
                b[nt][1] = *(const unsigned*)(base + 8);
            }
            #pragma unroll
            for (int mt = 0; mt < 2; ++mt)
                #pragma unroll
                for (int nt = 0; nt < 4; ++nt)
                    mma_f16(acc[mt][nt], a[mt][0], a[mt][1], a[mt][2], a[mt][3],
                            b[nt][0], b[nt][1]);
        }
    }

    // Writeback fp16 (Q scaled by 1/8)
    #pragma unroll
    for (int nt = 0; nt < 4; ++nt) {
        const int col = wn + nt*8 + 2*tg;
        float bx = bias[col], by = bias[col+1];
        #pragma unroll
        for (int mt = 0; mt < 2; ++mt) {
            int row = m0 + wm + mt*16 + g;
            __half2 h0 = __floats2half2_rn((acc[mt][nt][0]+bx)*osc, (acc[mt][nt][1]+by)*osc);
            __half2 h1 = __floats2half2_rn((acc[mt][nt][2]+bx)*osc, (acc[mt][nt][3]+by)*osc);
            *(__half2*)&O[(size_t)row*Dc + col]     = h0;
            *(__half2*)&O[(size_t)(row+8)*Dc + col] = h1;
        }
    }
}

// ---------------------------------------------------------------------------
// Kernel 1b: V -> V^T per batch.  grid = (Tc/64, Bc), block 256.
// ---------------------------------------------------------------------------
__global__ __launch_bounds__(256) void vtrans_kernel()
{
    __shared__ __half tile[64*66];
    const int t0 = blockIdx.x * 64;
    const int b  = blockIdx.y;
    const size_t bT = (size_t)b * Tc;
    const int tid = threadIdx.x;

    #pragma unroll
    for (int j = 0; j < 8; ++j) {
        int o = tid + 256*j;            // b32 index over 64x32
        int r = o >> 5, c = o & 31;
        *(unsigned*)&tile[r*66 + 2*c] =
            *(const unsigned*)&g_Vh[(bT + t0 + r)*Dc + 2*c];
    }
    __syncthreads();
    #pragma unroll
    for (int j = 0; j < 8; ++j) {
        int o = tid + 256*j;
        int d = o >> 5, c = o & 31;
        __half2 h = __halves2half2(tile[(2*c)*66 + d], tile[(2*c+1)*66 + d]);
        *(__half2*)&g_VTh[((size_t)b*Dc + d)*Tc + t0 + 2*c] = h;
    }
}

// ---------------------------------------------------------------------------
// Kernel 2: fp16 m16n8k16 flash attention, split-KV, cp.async.
// grid = (MAXC2, NQ2, B), block = 256 (8 warps).
// FIXED staging: 256 threads -> l_row = tid>>2 covers all 64 rows directly;
// each thread loads lo/hi 32-half chunks of its row for K and VT (no j loop).
// ---------------------------------------------------------------------------
__global__ __launch_bounds__(256, 2) void attn_kernel()
{
    const int c = blockIdx.x;
    const int i = blockIdx.y;
    const int b = blockIdx.z;
    const int ktot = 2*(i+1);
    const int kt0 = c * SCH;
    if (kt0 >= ktot) return;
    const int kt1 = min(kt0 + SCH, ktot);

    extern __shared__ __align__(16) __half smem[];
    __half* Ksm = smem;                  // [2][64*SKS2]
    __half* Tsm = smem + 2*64*SKS2;      // [2][64*SKS2]

    const int tid = threadIdx.x;
    const int w = tid >> 5, lane = tid & 31;
    const int g = lane >> 2, tg = lane & 3;
    const int qrow = i*QT + w*16;
    const size_t bT = (size_t)b * Tc;

    // staging map: one row per 4 threads; 4 chunk-pairs per row
    const int l_row = tid >> 2;          // 0..63
    const int l_c16 = tid & 3;           // 0..3

    // Prologue: stage tile kt0 into buffer 0
    {
        const __half* Kg = &g_Kh[(bT + kt0*64 + l_row)*Dc];
        const __half* Vg = &g_VTh[((size_t)b*Dc + l_row)*Tc + kt0*64];
        cp16(&Ksm[l_row*SKS2 + l_c16*8],      Kg + l_c16*8);
        cp16(&Ksm[l_row*SKS2 + 32 + l_c16*8], Kg + 32 + l_c16*8);
        cp16(&Tsm[l_row*SKS2 + l_c16*8],      Vg + l_c16*8);
        cp16(&Tsm[l_row*SKS2 + 32 + l_c16*8], Vg + 32 + l_c16*8);
        CP_COMMIT();
    }

    // Q A-fragments (4 k16 chunks x 4 regs), fp16 from gmem
    unsigned qa[4][4];
    {
        const __half* Qp = &g_Qh[(bT + qrow)*Dc];
        #pragma unroll
        for (int kc = 0; kc < 4; ++kc) {
            qa[kc][0] = *(const unsigned*)&Qp[(g  )*Dc + kc*16 + 2*tg];
            qa[kc][1] = *(const unsigned*)&Qp[(g+8)*Dc + kc*16 + 2*tg];
            qa[kc][2] = *(const unsigned*)&Qp[(g  )*Dc + kc*16 + 8 + 2*tg];
            qa[kc][3] = *(const unsigned*)&Qp[(g+8)*Dc + kc*16 + 8 + 2*tg];
        }
    }

    float o[8][4];
    #pragma unroll
    for (int nt = 0; nt < 8; ++nt)
        #pragma unroll
        for (int q = 0; q < 4; ++q) o[nt][q] = 0.f;
    float m0v = -1e30f, m1v = -1e30f, l0 = 0.f, l1 = 0.f;

    for (int kt = kt0; kt < kt1; ++kt) {
        const int buf = (kt - kt0) & 1;
        const __half* ks = Ksm + buf*64*SKS2;
        const __half* vs = Tsm + buf*64*SKS2;
        __half* kn = Ksm + (buf^1)*64*SKS2;
        __half* vn = Tsm + (buf^1)*64*SKS2;

        __syncthreads();
        if (kt + 1 < kt1) {
            const __half* Kg = &g_Kh[(bT + (kt+1)*64 + l_row)*Dc];
            const __half* Vg = &g_VTh[((size_t)b*Dc + l_row)*Tc + (kt+1)*64];
            cp16(&kn[l_row*SKS2 + l_c16*8],      Kg + l_c16*8);
            cp16(&kn[l_row*SKS2 + 32 + l_c16*8], Kg + 32 + l_c16*8);
            cp16(&vn[l_row*SKS2 + l_c16*8],      Vg + l_c16*8);
            cp16(&vn[l_row*SKS2 + 32 + l_c16*8], Vg + 32 + l_c16*8);
        }
        CP_COMMIT();
        CP_WAIT1();
        __syncthreads();

        const int kb = kt * 64;
        if (kb <= qrow + 15) {
            // --- S = Q @ K^T ---
            float s[8][4];
            #pragma unroll
            for (int nt = 0; nt < 8; ++nt)
                { s[nt][0]=0.f; s[nt][1]=0.f; s[nt][2]=0.f; s[nt][3]=0.f; }
            #pragma unroll
            for (int kc = 0; kc < 4; ++kc) {
                #pragma unroll
                for (int nt = 0; nt < 8; ++nt) {
                    const __half* kp = &ks[(nt*8 + g)*SKS2 + kc*16 + 2*tg];
                    mma_f16(s[nt], qa[kc][0], qa[kc][1], qa[kc][2], qa[kc][3],
                            *(const unsigned*)kp, *(const unsigned*)(kp + 8));
                }
            }

            // --- causal mask ---
            if (kb + 63 > qrow) {
                const int r0 = qrow + g, r1 = r0 + 8;
                #pragma unroll
                for (int nt = 0; nt < 8; ++nt) {
                    int col = kb + nt*8 + 2*tg;
                    if (col   > r0) s[nt][0] = -1e30f;
                    if (col+1 > r0) s[nt][1] = -1e30f;
                    if (col   > r1) s[nt][2] = -1e30f;
                    if (col+1 > r1) s[nt][3] = -1e30f;
                }
            }

            // --- online softmax (warp-local; rows g and g+8) ---
            float rm0 = -1e30f, rm1 = -1e30f;
            #pragma unroll
            for (int nt = 0; nt < 8; ++nt) {
                rm0 = fmaxf(rm0, fmaxf(s[nt][0], s[nt][1]));
                rm1 = fmaxf(rm1, fmaxf(s[nt][2], s[nt][3]));
            }
            rm0 = fmaxf(rm0, __shfl_xor_sync(0xffffffffu, rm0, 1));
            rm0 = fmaxf(rm0, __shfl_xor_sync(0xffffffffu, rm0, 2));
            rm1 = fmaxf(rm1, __shfl_xor_sync(0xffffffffu, rm1, 1));
            rm1 = fmaxf(rm1, __shfl_xor_sync(0xffffffffu, rm1, 2));
            const float mn0 = fmaxf(m0v, rm0), mn1 = fmaxf(m1v, rm1);
            const float f0 = __expf(m0v - mn0), f1 = __expf(m1v - mn1);
            m0v = mn0; m1v = mn1;

            float rs0 = 0.f, rs1 = 0.f;
            #pragma unroll
            for (int nt = 0; nt < 8; ++nt) {
                s[nt][0] = __expf(s[nt][0] - mn0);
                s[nt][1] = __expf(s[nt][1] - mn0);
                s[nt][2] = __expf(s[nt][2] - mn1);
                s[nt][3] = __expf(s[nt][3] - mn1);
                rs0 += s[nt][0] + s[nt][1];
                rs1 += s[nt][2] + s[nt][3];
            }
            rs0 += __shfl_xor_sync(0xffffffffu, rs0, 1);
            rs0 += __shfl_xor_sync(0xffffffffu, rs0, 2);
            rs1 += __shfl_xor_sync(0xffffffffu, rs1, 1);
            rs1 += __shfl_xor_sync(0xffffffffu, rs1, 2);
            l0 = l0*f0 + rs0;
            l1 = l1*f1 + rs1;
            #pragma unroll
            for (int nt = 0; nt < 8; ++nt) {
                o[nt][0] *= f0; o[nt][1] *= f0;
                o[nt][2] *= f1; o[nt][3] *= f1;
            }

            // --- O += P @ V : C-fragments pack directly into A-fragments ---
            #pragma unroll
            for (int kc = 0; kc < 4; ++kc) {
                unsigned pa0 = packh2(s[2*kc  ][0], s[2*kc  ][1]);
                unsigned pa1 = packh2(s[2*kc  ][2], s[2*kc  ][3]);
                unsigned pa2 = packh2(s[2*kc+1][0], s[2*kc+1][1]);
                unsigned pa3 = packh2(s[2*kc+1][2], s[2*kc+1][3]);
                #pragma unroll
                for (int nt = 0; nt < 8; ++nt) {
                    const __half* vp = &vs[(nt*8 + g)*SKS2 + kc*16 + 2*tg];
                    mma_f16(o[nt], pa0, pa1, pa2, pa3,
                            *(const unsigned*)vp, *(const unsigned*)(vp + 8));
                }
            }
        }
    }

    // Store partials (fp32) + per-row m, l
    const size_t pbase = ((size_t)(b*NQ2 + i)*MAXC2 + c) * (QT*Dc);
    #pragma unroll
    for (int nt = 0; nt < 8; ++nt) {
        const int colb = nt*8 + 2*tg;
        float2 o0; o0.x = o[nt][0]; o0.y = o[nt][1];
        float2 o1; o1.x = o[nt][2]; o1.y = o[nt][3];
        *(float2*)&g_Op2[pbase + (size_t)(w*16 + g    )*Dc + colb] = o0;
        *(float2*)&g_Op2[pbase + (size_t)(w*16 + g + 8)*Dc + colb] = o1;
    }
    if (tg == 0) {
        const size_t rb = ((size_t)(b*NQ2 + i)*MAXC2 + c) * QT + w*16;
        g_m2[rb + g]     = m0v;  g_l2[rb + g]     = l0;
        g_m2[rb + g + 8] = m1v;  g_l2[rb + g + 8] = l1;
    }
}

// ---------------------------------------------------------------------------
// Kernel 3: combine split-KV partials. grid = (NQ2, B, 8), block 256.
// ---------------------------------------------------------------------------
__global__ __launch_bounds__(256) void combine_kernel(float* __restrict__ out)
{
    const int i = blockIdx.x;
    const int b = blockIdx.y;
    const int nc = (2*(i+1) + SCH - 1) / SCH;
    const size_t cb = (size_t)(b*NQ2 + i) * MAXC2;

    const int f = blockIdx.z * 256 + threadIdx.x;
    const int row = f >> 4;

    float M = -1e30f;
    float mm[MAXC2];
    #pragma unroll
    for (int cc = 0; cc < MAXC2; ++cc) {
        if (cc < nc) {
            mm[cc] = g_m2[(cb + cc)*QT + row];
            M = fmaxf(M, mm[cc]);
        }
    }
    float L = 0.f;
    float4 o; o.x = o.y = o.z = o.w = 0.f;
    #pragma unroll
    for (int cc = 0; cc < MAXC2; ++cc) {
        if (cc < nc) {
            float wgt = __expf(mm[cc] - M);
            L += wgt * g_l2[(cb + cc)*QT + row];
            float4 p = ((const float4*)g_Op2)[(cb + cc)*(QT*Dc/4) + f];
            o.x += wgt*p.x; o.y += wgt*p.y; o.z += wgt*p.z; o.w += wgt*p.w;
        }
    }
    float inv = 1.f / L;
    o.x *= inv; o.y *= inv; o.z *= inv; o.w *= inv;
    ((float4*)out)[((size_t)b*Tc + i*QT + row)*(Dc/4) + (f & 15)] = o;
}

// ---------------------------------------------------------------------------
extern "C" void kernel_launch(void* const* d_in, const int* in_sizes, int n_in,
                              void* d_out, int out_size)
{
    const float* x  = (const float*)d_in[0];
    const float* Wq = (const float*)d_in[1];
    const float* bq = (const float*)d_in[2];
    const float* Wk = (const float*)d_in[3];
    const float* bk = (const float*)d_in[4];
    const float* Wv = (const float*)d_in[5];
    const float* bv = (const float*)d_in[6];
    float* out = (float*)d_out;

    prepx_kernel<<<(int)((size_t)BT*Cc/8/256), 256>>>(x);
    prepw_kernel<<<3*Dc*Cc/256, 256>>>(Wq, Wk, Wv);

    const int qkv_smem = 4*64*SA2 * (int)sizeof(__half);   // 20,480 B
    cudaFuncSetAttribute(qkv_kernel, cudaFuncAttributeMaxDynamicSharedMemorySize, qkv_smem);
    dim3 g1(BT/64, 3);
    qkv_kernel<<<g1, 128, qkv_smem>>>(bq, bk, bv);

    vtrans_kernel<<<dim3(Tc/64, Bc), 256>>>();

    const int attn_smem = 4*64*SKS2 * (int)sizeof(__half); // 36,864 B
    cudaFuncSetAttribute(attn_kernel, cudaFuncAttributeMaxDynamicSharedMemorySize, attn_smem);
    dim3 g2(MAXC2, NQ2, Bc);
    attn_kernel<<<g2, 256, attn_smem>>>();

    dim3 g3(NQ2, Bc, 8);
    combine_kernel<<<g3, 256>>>(out);
}

// round 11
// speedup vs baseline: 1.4869x; 1.1345x over previous
#include <cuda_runtime.h>
#include <cuda_fp16.h>
#include <cstdint>

#define Bc 4
#define Tc 2048
#define Cc 1024
#define Dc 64
#define BT (Bc*Tc)

#define QT   128
#define NQ2  (Tc/QT)
#define SCH  4
#define MAXC2 8
#define SKS2 72            // attn K/V smem row stride in halves (144B, ≡4w mod 32)
#define SA2  40            // qkv smem row stride in halves (80B, 20w: conflict-free)
#define BKH  32            // qkv k-chunk in halves

// Scratch (allocation-free rule => __device__ globals)
__device__ __half g_xh [(size_t)BT*Cc];              // fp16 x
__device__ __half g_WhT[3*Dc*Cc];                    // fp16 W^T [proj][n][k]
__device__ __half g_Qh [BT*Dc];                      // fp16 Q (pre-scaled)
__device__ __half g_Kh [BT*Dc];
__device__ __half g_Vh [BT*Dc];
__device__ float  g_Op2[(size_t)Bc*NQ2*MAXC2*QT*Dc];
__device__ float  g_m2[Bc*NQ2*MAXC2*QT];
__device__ float  g_l2[Bc*NQ2*MAXC2*QT];

__device__ __forceinline__ unsigned packh2(float lo, float hi) {
    __half2 h = __floats2half2_rn(lo, hi);
    return *(unsigned*)&h;
}

__device__ __forceinline__ unsigned smem_u32(const void* p) {
    return (unsigned)__cvta_generic_to_shared(p);
}

__device__ __forceinline__ void mma_f16(float c[4], unsigned a0, unsigned a1,
                                        unsigned a2, unsigned a3,
                                        unsigned b0, unsigned b1) {
    asm volatile(
        "mma.sync.aligned.m16n8k16.row.col.f32.f16.f16.f32 "
        "{%0,%1,%2,%3}, {%4,%5,%6,%7}, {%8,%9}, {%0,%1,%2,%3};"
        : "+f"(c[0]), "+f"(c[1]), "+f"(c[2]), "+f"(c[3])
        : "r"(a0), "r"(a1), "r"(a2), "r"(a3), "r"(b0), "r"(b1));
}

__device__ __forceinline__ void ldsm_x4(unsigned& r0, unsigned& r1,
                                        unsigned& r2, unsigned& r3, unsigned a) {
    asm volatile("ldmatrix.sync.aligned.m8n8.x4.shared.b16 {%0,%1,%2,%3}, [%4];"
                 : "=r"(r0), "=r"(r1), "=r"(r2), "=r"(r3) : "r"(a));
}
__device__ __forceinline__ void ldsm_x4_t(unsigned& r0, unsigned& r1,
                                          unsigned& r2, unsigned& r3, unsigned a) {
    asm volatile("ldmatrix.sync.aligned.m8n8.x4.trans.shared.b16 {%0,%1,%2,%3}, [%4];"
                 : "=r"(r0), "=r"(r1), "=r"(r2), "=r"(r3) : "r"(a));
}

__device__ __forceinline__ void cp16(void* dst_smem, const void* src) {
    unsigned d = (unsigned)__cvta_generic_to_shared(dst_smem);
    asm volatile("cp.async.ca.shared.global [%0], [%1], 16;" :: "r"(d), "l"(src));
}
#define CP_COMMIT() asm volatile("cp.async.commit_group;")
#define CP_WAIT1()  asm volatile("cp.async.wait_group 1;")

// ---------------------------------------------------------------------------
// Kernel 0a: x -> fp16.  grid = BT*Cc/8/256 = 4096, block 256.
// ---------------------------------------------------------------------------
__global__ __launch_bounds__(256) void prepx_kernel(const float* __restrict__ x)
{
    size_t idx = (size_t)blockIdx.x * 256 + threadIdx.x;
    const float4* xg = (const float4*)x;
    float4 v0 = xg[2*idx], v1 = xg[2*idx + 1];
    __half2 h0 = __floats2half2_rn(v0.x, v0.y);
    __half2 h1 = __floats2half2_rn(v0.z, v0.w);
    __half2 h2 = __floats2half2_rn(v1.x, v1.y);
    __half2 h3 = __floats2half2_rn(v1.z, v1.w);
    uint4 o;
    o.x = *(unsigned*)&h0; o.y = *(unsigned*)&h1;
    o.z = *(unsigned*)&h2; o.w = *(unsigned*)&h3;
    ((uint4*)g_xh)[idx] = o;
}

// ---------------------------------------------------------------------------
// Kernel 0b: W^T -> fp16.  grid = 768, block 256.
// ---------------------------------------------------------------------------
__global__ __launch_bounds__(256) void prepw_kernel(
    const float* __restrict__ Wq, const float* __restrict__ Wk,
    const float* __restrict__ Wv)
{
    int e = blockIdx.x * 256 + threadIdx.x;
    int proj = e >> 16;
    int r = e & 65535;
    int k = r >> 6;
    int n = r & 63;
    const float* W = (proj == 0) ? Wq : (proj == 1) ? Wk : Wv;
    g_WhT[(size_t)proj*(Dc*Cc) + (size_t)n*Cc + k] = __float2half_rn(W[(size_t)k*Dc + n]);
}

// ---------------------------------------------------------------------------
// Kernel 1: QKV projection, fp16 m16n8k16 MMA + ldmatrix, 2-stage cp.async.
// grid = (BT/64, 3), block = 128 (4 warps). Tile 64x64, k-chunk 32 halves.
// ---------------------------------------------------------------------------
__global__ __launch_bounds__(128) void qkv_kernel(
    const float* __restrict__ bq, const float* __restrict__ bk,
    const float* __restrict__ bv)
{
    extern __shared__ __align__(16) __half sm[];
    __half* As = sm;                    // [2][64*SA2]
    __half* Bs = sm + 2*64*SA2;         // [2][64*SA2]

    const int tid = threadIdx.x;
    const int which = blockIdx.y;
    const __half* WT = g_WhT + (size_t)which * (Dc*Cc);
    const float* bias = (which == 0) ? bq : (which == 1) ? bk : bv;
    __half* O = (which == 0) ? g_Qh : (which == 1) ? g_Kh : g_Vh;
    const float osc = (which == 0) ? 0.125f : 1.0f;

    const int m0 = blockIdx.x * 64;
    const int w  = tid >> 5;
    const int lane = tid & 31;
    const int g  = lane >> 2;
    const int tg = lane & 3;
    const int wm = (w & 1) * 32;
    const int wn = (w >> 1) * 32;

    // ldmatrix lane decomposition
    const int lr8 = lane & 7;            // row within 8-row matrix
    const int lm1 = (lane >> 3) & 1;     // matrix pair selector bit
    const int lm2 = lane >> 4;           // matrix quad selector bit

    const int l_row = tid >> 2, l_c16 = tid & 3;

    float acc[2][4][4];
    #pragma unroll
    for (int mt = 0; mt < 2; ++mt)
        #pragma unroll
        for (int nt = 0; nt < 4; ++nt)
            #pragma unroll
            for (int q = 0; q < 4; ++q) acc[mt][nt][q] = 0.f;

    // Prologue: stage kc=0
    {
        #pragma unroll
        for (int j = 0; j < 2; ++j) {
            int row = l_row + 32*j;
            cp16(&As[row*SA2 + l_c16*8], &g_xh[(size_t)(m0 + row)*Cc + l_c16*8]);
            cp16(&Bs[row*SA2 + l_c16*8], &WT[(size_t)row*Cc + l_c16*8]);
        }
        CP_COMMIT();
    }

    const int NIT = Cc / BKH;            // 32
    for (int kc = 0; kc < NIT; ++kc) {
        const int buf = kc & 1;
        __half* Ab = As + buf*64*SA2;
        __half* Bb = Bs + buf*64*SA2;
        __half* An = As + (buf^1)*64*SA2;
        __half* Bn = Bs + (buf^1)*64*SA2;

        __syncthreads();
        if (kc + 1 < NIT) {
            #pragma unroll
            for (int j = 0; j < 2; ++j) {
                int row = l_row + 32*j;
                cp16(&An[row*SA2 + l_c16*8],
                     &g_xh[(size_t)(m0 + row)*Cc + (kc+1)*BKH + l_c16*8]);
                cp16(&Bn[row*SA2 + l_c16*8],
                     &WT[(size_t)row*Cc + (kc+1)*BKH + l_c16*8]);
            }
        }
        CP_COMMIT();
        CP_WAIT1();
        __syncthreads();

        #pragma unroll
        for (int ks = 0; ks < 2; ++ks) {
            const int k0 = ks * 16;
            unsigned a[2][4], b[4][2];
            // A fragments: M0=(rows 0-7,k0) M1=(rows 8-15,k0) M2=(rows,k0+8) M3=(+8,+8)
            #pragma unroll
            for (int mt = 0; mt < 2; ++mt) {
                unsigned ad = smem_u32(
                    &Ab[(wm + mt*16 + lr8 + lm1*8)*SA2 + k0 + lm2*8]);
                ldsm_x4(a[mt][0], a[mt][1], a[mt][2], a[mt][3], ad);
            }
            // B fragments: non-trans on WT[n][k] rows; x4 covers 2 nt
            #pragma unroll
            for (int ntp = 0; ntp < 2; ++ntp) {
                unsigned bd = smem_u32(
                    &Bb[(wn + ntp*16 + lr8 + lm2*8)*SA2 + k0 + lm1*8]);
                ldsm_x4(b[ntp*2][0], b[ntp*2][1], b[ntp*2+1][0], b[ntp*2+1][1], bd);
            }
            #pragma unroll
            for (int mt = 0; mt < 2; ++mt)
                #pragma unroll
                for (int nt = 0; nt < 4; ++nt)
                    mma_f16(acc[mt][nt], a[mt][0], a[mt][1], a[mt][2], a[mt][3],
                            b[nt][0], b[nt][1]);
        }
    }

    // Writeback fp16 (Q scaled by 1/8)
    #pragma unroll
    for (int nt = 0; nt < 4; ++nt) {
        const int col = wn + nt*8 + 2*tg;
        float bx = bias[col], by = bias[col+1];
        #pragma unroll
        for (int mt = 0; mt < 2; ++mt) {
            int row = m0 + wm + mt*16 + g;
            __half2 h0 = __floats2half2_rn((acc[mt][nt][0]+bx)*osc, (acc[mt][nt][1]+by)*osc);
            __half2 h1 = __floats2half2_rn((acc[mt][nt][2]+bx)*osc, (acc[mt][nt][3]+by)*osc);
            *(__half2*)&O[(size_t)row*Dc + col]     = h0;
            *(__half2*)&O[(size_t)(row+8)*Dc + col] = h1;
        }
    }
}

// ---------------------------------------------------------------------------
// Kernel 2: fp16 m16n8k16 flash attention, split-KV, cp.async + ldmatrix.
// grid = (MAXC2, NQ2, B), block = 256 (8 warps). V stays row-major [t][d];
// PV B-fragments come from ldmatrix.x4.trans (no VT materialization).
// ---------------------------------------------------------------------------
__global__ __launch_bounds__(256, 2) void attn_kernel()
{
    const int c = blockIdx.x;
    const int i = blockIdx.y;
    const int b = blockIdx.z;
    const int ktot = 2*(i+1);
    const int kt0 = c * SCH;
    if (kt0 >= ktot) return;
    const int kt1 = min(kt0 + SCH, ktot);

    extern __shared__ __align__(16) __half smem[];
    __half* Ksm = smem;                  // [2][64*SKS2]
    __half* Vsm = smem + 2*64*SKS2;      // [2][64*SKS2]

    const int tid = threadIdx.x;
    const int w = tid >> 5, lane = tid & 31;
    const int g = lane >> 2, tg = lane & 3;
    const int qrow = i*QT + w*16;
    const size_t bT = (size_t)b * Tc;

    const int lr8 = lane & 7;
    const int lm1 = (lane >> 3) & 1;
    const int lm2 = lane >> 4;

    // staging: one row per 4 threads, lo/hi 32-half chunks
    const int l_row = tid >> 2;          // 0..63
    const int l_c16 = tid & 3;           // 0..3

    // Prologue: stage tile kt0
    {
        const __half* Kg = &g_Kh[(bT + kt0*64 + l_row)*Dc];
        const __half* Vg = &g_Vh[(bT + kt0*64 + l_row)*Dc];
        cp16(&Ksm[l_row*SKS2 + l_c16*8],      Kg + l_c16*8);
        cp16(&Ksm[l_row*SKS2 + 32 + l_c16*8], Kg + 32 + l_c16*8);
        cp16(&Vsm[l_row*SKS2 + l_c16*8],      Vg + l_c16*8);
        cp16(&Vsm[l_row*SKS2 + 32 + l_c16*8], Vg + 32 + l_c16*8);
        CP_COMMIT();
    }

    // Q A-fragments
    unsigned qa[4][4];
    {
        const __half* Qp = &g_Qh[(bT + qrow)*Dc];
        #pragma unroll
        for (int kc = 0; kc < 4; ++kc) {
            qa[kc][0] = *(const unsigned*)&Qp[(g  )*Dc + kc*16 + 2*tg];
            qa[kc][1] = *(const unsigned*)&Qp[(g+8)*Dc + kc*16 + 2*tg];
            qa[kc][2] = *(const unsigned*)&Qp[(g  )*Dc + kc*16 + 8 + 2*tg];
            qa[kc][3] = *(const unsigned*)&Qp[(g+8)*Dc + kc*16 + 8 + 2*tg];
        }
    }

    float o[8][4];
    #pragma unroll
    for (int nt = 0; nt < 8; ++nt)
        #pragma unroll
        for (int q = 0; q < 4; ++q) o[nt][q] = 0.f;
    float m0v = -1e30f, m1v = -1e30f, l0 = 0.f, l1 = 0.f;

    for (int kt = kt0; kt < kt1; ++kt) {
        const int buf = (kt - kt0) & 1;
        const __half* ks = Ksm + buf*64*SKS2;
        const __half* vs = Vsm + buf*64*SKS2;
        __half* kn = Ksm + (buf^1)*64*SKS2;
        __half* vn = Vsm + (buf^1)*64*SKS2;

        __syncthreads();
        if (kt + 1 < kt1) {
            const __half* Kg = &g_Kh[(bT + (kt+1)*64 + l_row)*Dc];
            const __half* Vg = &g_Vh[(bT + (kt+1)*64 + l_row)*Dc];
            cp16(&kn[l_row*SKS2 + l_c16*8],      Kg + l_c16*8);
            cp16(&kn[l_row*SKS2 + 32 + l_c16*8], Kg + 32 + l_c16*8);
            cp16(&vn[l_row*SKS2 + l_c16*8],      Vg + l_c16*8);
            cp16(&vn[l_row*SKS2 + 32 + l_c16*8], Vg + 32 + l_c16*8);
        }
        CP_COMMIT();
        CP_WAIT1();
        __syncthreads();

        const int kb = kt * 64;
        if (kb <= qrow + 15) {
            // --- S = Q @ K^T : K B-fragments via non-trans ldmatrix ---
            float s[8][4];
            #pragma unroll
            for (int nt = 0; nt < 8; ++nt)
                { s[nt][0]=0.f; s[nt][1]=0.f; s[nt][2]=0.f; s[nt][3]=0.f; }
            #pragma unroll
            for (int kc = 0; kc < 4; ++kc) {
                unsigned kb_[8][2];
                #pragma unroll
                for (int ntp = 0; ntp < 4; ++ntp) {
                    unsigned ad = smem_u32(
                        &ks[(ntp*16 + lr8 + lm2*8)*SKS2 + kc*16 + lm1*8]);
                    ldsm_x4(kb_[ntp*2][0], kb_[ntp*2][1],
                            kb_[ntp*2+1][0], kb_[ntp*2+1][1], ad);
                }
                #pragma unroll
                for (int nt = 0; nt < 8; ++nt)
                    mma_f16(s[nt], qa[kc][0], qa[kc][1], qa[kc][2], qa[kc][3],
                            kb_[nt][0], kb_[nt][1]);
            }

            // --- causal mask ---
            if (kb + 63 > qrow) {
                const int r0 = qrow + g, r1 = r0 + 8;
                #pragma unroll
                for (int nt = 0; nt < 8; ++nt) {
                    int col = kb + nt*8 + 2*tg;
                    if (col   > r0) s[nt][0] = -1e30f;
                    if (col+1 > r0) s[nt][1] = -1e30f;
                    if (col   > r1) s[nt][2] = -1e30f;
                    if (col+1 > r1) s[nt][3] = -1e30f;
                }
            }

            // --- online softmax (warp-local; rows g and g+8) ---
            float rm0 = -1e30f, rm1 = -1e30f;
            #pragma unroll
            for (int nt = 0; nt < 8; ++nt) {
                rm0 = fmaxf(rm0, fmaxf(s[nt][0], s[nt][1]));
                rm1 = fmaxf(rm1, fmaxf(s[nt][2], s[nt][3]));
            }
            rm0 = fmaxf(rm0, __shfl_xor_sync(0xffffffffu, rm0, 1));
            rm0 = fmaxf(rm0, __shfl_xor_sync(0xffffffffu, rm0, 2));
            rm1 = fmaxf(rm1, __shfl_xor_sync(0xffffffffu, rm1, 1));
            rm1 = fmaxf(rm1, __shfl_xor_sync(0xffffffffu, rm1, 2));
            const float mn0 = fmaxf(m0v, rm0), mn1 = fmaxf(m1v, rm1);
            const float f0 = __expf(m0v - mn0), f1 = __expf(m1v - mn1);
            m0v = mn0; m1v = mn1;

            float rs0 = 0.f, rs1 = 0.f;
            #pragma unroll
            for (int nt = 0; nt < 8; ++nt) {
                s[nt][0] = __expf(s[nt][0] - mn0);
                s[nt][1] = __expf(s[nt][1] - mn0);
                s[nt][2] = __expf(s[nt][2] - mn1);
                s[nt][3] = __expf(s[nt][3] - mn1);
                rs0 += s[nt][0] + s[nt][1];
                rs1 += s[nt][2] + s[nt][3];
            }
            rs0 += __shfl_xor_sync(0xffffffffu, rs0, 1);
            rs0 += __shfl_xor_sync(0xffffffffu, rs0, 2);
            rs1 += __shfl_xor_sync(0xffffffffu, rs1, 1);
            rs1 += __shfl_xor_sync(0xffffffffu, rs1, 2);
            l0 = l0*f0 + rs0;
            l1 = l1*f1 + rs1;
            #pragma unroll
            for (int nt = 0; nt < 8; ++nt) {
                o[nt][0] *= f0; o[nt][1] *= f0;
                o[nt][2] *= f1; o[nt][3] *= f1;
            }

            // --- O += P @ V : P packs into A-fragments; V B-fragments
            //     via ldmatrix.x4.trans on row-major V[t][d] ---
            #pragma unroll
            for (int kc = 0; kc < 4; ++kc) {
                unsigned pa0 = packh2(s[2*kc  ][0], s[2*kc  ][1]);
                unsigned pa1 = packh2(s[2*kc  ][2], s[2*kc  ][3]);
                unsigned pa2 = packh2(s[2*kc+1][0], s[2*kc+1][1]);
                unsigned pa3 = packh2(s[2*kc+1][2], s[2*kc+1][3]);
                unsigned vb[8][2];
                #pragma unroll
                for (int ntp = 0; ntp < 4; ++ntp) {
                    // M0=(t rows kc*16, d ntp*16) M1=(t+8, d) M2=(t, d+8) M3=(t+8, d+8)
                    unsigned ad = smem_u32(
                        &vs[(kc*16 + lr8 + lm1*8)*SKS2 + ntp*16 + lm2*8]);
                    ldsm_x4_t(vb[ntp*2][0], vb[ntp*2][1],
                              vb[ntp*2+1][0], vb[ntp*2+1][1], ad);
                }
                #pragma unroll
                for (int nt = 0; nt < 8; ++nt)
                    mma_f16(o[nt], pa0, pa1, pa2, pa3, vb[nt][0], vb[nt][1]);
            }
        }
    }

    // Store partials (fp32) + per-row m, l
    const size_t pbase = ((size_t)(b*NQ2 + i)*MAXC2 + c) * (QT*Dc);
    #pragma unroll
    for (int nt = 0; nt < 8; ++nt) {
        const int colb = nt*8 + 2*tg;
        float2 o0; o0.x = o[nt][0]; o0.y = o[nt][1];
        float2 o1; o1.x = o[nt][2]; o1.y = o[nt][3];
        *(float2*)&g_Op2[pbase + (size_t)(w*16 + g    )*Dc + colb] = o0;
        *(float2*)&g_Op2[pbase + (size_t)(w*16 + g + 8)*Dc + colb] = o1;
    }
    if (tg == 0) {
        const size_t rb = ((size_t)(b*NQ2 + i)*MAXC2 + c) * QT + w*16;
        g_m2[rb + g]     = m0v;  g_l2[rb + g]     = l0;
        g_m2[rb + g + 8] = m1v;  g_l2[rb + g + 8] = l1;
    }
}

// ---------------------------------------------------------------------------
// Kernel 3: combine split-KV partials. grid = (NQ2, B, 8), block 256.
// ---------------------------------------------------------------------------
__global__ __launch_bounds__(256) void combine_kernel(float* __restrict__ out)
{
    const int i = blockIdx.x;
    const int b = blockIdx.y;
    const int nc = (2*(i+1) + SCH - 1) / SCH;
    const size_t cb = (size_t)(b*NQ2 + i) * MAXC2;

    const int f = blockIdx.z * 256 + threadIdx.x;
    const int row = f >> 4;

    float M = -1e30f;
    float mm[MAXC2];
    #pragma unroll
    for (int cc = 0; cc < MAXC2; ++cc) {
        if (cc < nc) {
            mm[cc] = g_m2[(cb + cc)*QT + row];
            M = fmaxf(M, mm[cc]);
        }
    }
    float L = 0.f;
    float4 o; o.x = o.y = o.z = o.w = 0.f;
    #pragma unroll
    for (int cc = 0; cc < MAXC2; ++cc) {
        if (cc < nc) {
            float wgt = __expf(mm[cc] - M);
            L += wgt * g_l2[(cb + cc)*QT + row];
            float4 p = ((const float4*)g_Op2)[(cb + cc)*(QT*Dc/4) + f];
            o.x += wgt*p.x; o.y += wgt*p.y; o.z += wgt*p.z; o.w += wgt*p.w;
        }
    }
    float inv = 1.f / L;
    o.x *= inv; o.y *= inv; o.z *= inv; o.w *= inv;
    ((float4*)out)[((size_t)b*Tc + i*QT + row)*(Dc/4) + (f & 15)] = o;
}

// ---------------------------------------------------------------------------
extern "C" void kernel_launch(void* const* d_in, const int* in_sizes, int n_in,
                              void* d_out, int out_size)
{
    const float* x  = (const float*)d_in[0];
    const float* Wq = (const float*)d_in[1];
    const float* bq = (const float*)d_in[2];
    const float* Wk = (const float*)d_in[3];
    const float* bk = (const float*)d_in[4];
    const float* Wv = (const float*)d_in[5];
    const float* bv = (const float*)d_in[6];
    float* out = (float*)d_out;

    prepx_kernel<<<(int)((size_t)BT*Cc/8/256), 256>>>(x);
    prepw_kernel<<<3*Dc*Cc/256, 256>>>(Wq, Wk, Wv);

    const int qkv_smem = 4*64*SA2 * (int)sizeof(__half);   // 20,480 B
    cudaFuncSetAttribute(qkv_kernel, cudaFuncAttributeMaxDynamicSharedMemorySize, qkv_smem);
    dim3 g1(BT/64, 3);
    qkv_kernel<<<g1, 128, qkv_smem>>>(bq, bk, bv);

    const int attn_smem = 4*64*SKS2 * (int)sizeof(__half); // 36,864 B
    cudaFuncSetAttribute(attn_kernel, cudaFuncAttributeMaxDynamicSharedMemorySize, attn_smem);
    dim3 g2(MAXC2, NQ2, Bc);
    attn_kernel<<<g2, 256, attn_smem>>>();

    dim3 g3(NQ2, Bc, 8);
    combine_kernel<<<g3, 256>>>(out);
}